// round 1
// baseline (speedup 1.0000x reference)
#include <cuda_runtime.h>

#define NN 16384
#define BATCH 2048
#define DL 256
#define LL 64

// Scratch (static __device__ — no allocations allowed)
__device__ float g_pred_e[BATCH * 1536];   // 12.6 MB
__device__ float g_h[NN * LL];             // 4 MB
__device__ float g_row[NN];                // L_q - L_e per row
__device__ float g_part[1024];             // decoder block partials

// ---------------------------------------------------------------------------
// K1: pred_e = x @ W_e + b_e   (2048 x 1536, K=256)
// BM=128, BN=64, BK=16, 256 threads, 8x4 microtile
// ---------------------------------------------------------------------------
__global__ __launch_bounds__(256) void k1_gemm_e(const float* __restrict__ x,
                                                 const float* __restrict__ We,
                                                 const float* __restrict__ be) {
    __shared__ float As[16][128];
    __shared__ float Bs[16][64];
    const int bx = blockIdx.x;   // 0..23  (N)
    const int by = blockIdx.y;   // 0..15  (M)
    const int tid = threadIdx.x;
    const int tx = tid & 15;     // N dir
    const int ty = tid >> 4;     // M dir
    const int ar = tid >> 2;         // 0..63
    const int ac = (tid & 3) << 2;   // 0,4,8,12
    const int br = tid >> 4;         // 0..15
    const int bc = (tid & 15) << 2;  // 0..60

    float acc[8][4];
#pragma unroll
    for (int i = 0; i < 8; i++)
#pragma unroll
        for (int j = 0; j < 4; j++) acc[i][j] = 0.f;

    for (int k0 = 0; k0 < 256; k0 += 16) {
        float4 a0 = *(const float4*)(x + (by * 128 + ar) * 256 + k0 + ac);
        float4 a1 = *(const float4*)(x + (by * 128 + ar + 64) * 256 + k0 + ac);
        As[ac + 0][ar] = a0.x; As[ac + 1][ar] = a0.y;
        As[ac + 2][ar] = a0.z; As[ac + 3][ar] = a0.w;
        As[ac + 0][ar + 64] = a1.x; As[ac + 1][ar + 64] = a1.y;
        As[ac + 2][ar + 64] = a1.z; As[ac + 3][ar + 64] = a1.w;
        float4 b0 = *(const float4*)(We + (k0 + br) * 1536 + bx * 64 + bc);
        *(float4*)&Bs[br][bc] = b0;
        __syncthreads();
#pragma unroll
        for (int kk = 0; kk < 16; kk++) {
            float4 av0 = *(const float4*)&As[kk][ty * 8];
            float4 av1 = *(const float4*)&As[kk][ty * 8 + 4];
            float4 bv = *(const float4*)&Bs[kk][tx * 4];
            float av[8] = {av0.x, av0.y, av0.z, av0.w, av1.x, av1.y, av1.z, av1.w};
            float bw[4] = {bv.x, bv.y, bv.z, bv.w};
#pragma unroll
            for (int i = 0; i < 8; i++)
#pragma unroll
                for (int j = 0; j < 4; j++) acc[i][j] = fmaf(av[i], bw[j], acc[i][j]);
        }
        __syncthreads();
    }
    float4 bias = *(const float4*)(be + bx * 64 + tx * 4);
#pragma unroll
    for (int i = 0; i < 8; i++) {
        float4 o;
        o.x = acc[i][0] + bias.x; o.y = acc[i][1] + bias.y;
        o.z = acc[i][2] + bias.z; o.w = acc[i][3] + bias.w;
        *(float4*)&g_pred_e[(by * 128 + ty * 8 + i) * 1536 + bx * 64 + tx * 4] = o;
    }
}

// ---------------------------------------------------------------------------
// K2: encoder epilogue. One thread per (n, l). 4 rows per 256-thread block.
// Computes: softmax over comps, discrete sample, h, L_e; row scalar L_q - L_e.
// ---------------------------------------------------------------------------
__global__ __launch_bounds__(256) void k2_encoder(const float* __restrict__ u_e,
                                                  const float* __restrict__ r_in) {
    __shared__ float red[8];
    const int t = threadIdx.x;
    const int n = blockIdx.x * 4 + (t >> 6);
    const int l = t & 63;
    const int b = n & 2047;
    const float* pe = g_pred_e + b * 1536;

    float m[8], lp[8], a[8];
#pragma unroll
    for (int k = 0; k < 8; k++) {
        m[k]  = pe[k * 64 + l];
        lp[k] = pe[512 + k * 64 + l];
        a[k]  = pe[1024 + k * 64 + l];
    }
    float amax = a[0];
#pragma unroll
    for (int k = 1; k < 8; k++) amax = fmaxf(amax, a[k]);
    float e[8];
    float se = 0.f;
#pragma unroll
    for (int k = 0; k < 8; k++) { e[k] = __expf(a[k] - amax); se += e[k]; }
    const float lse_a = amax + __logf(se);
    const float inv_se = 1.f / se;

    // discrete sample: idx = #{k : r > cumsum(prob)} clipped to 7
    const float rv = r_in[n * 64 + l];
    float cacc = 0.f;
    int idx = 0;
#pragma unroll
    for (int k = 0; k < 8; k++) {
        cacc += e[k] * inv_se;
        idx += (rv > cacc) ? 1 : 0;
    }
    if (idx > 7) idx = 7;
    float msel = m[0], lpsel = lp[0];
#pragma unroll
    for (int k = 1; k < 8; k++)
        if (idx == k) { msel = m[k]; lpsel = lp[k]; }
    const float hv = fmaf(__expf(-0.5f * lpsel), u_e[n * 64 + l], msel);
    g_h[n * 64 + l] = hv;

    // L_e contribution: logsumexp_k( (a-lse_a) + 0.5 lp - 0.5 exp(lp)(h-m)^2 )
    float tv[8];
    float tmax = -1e30f;
#pragma unroll
    for (int k = 0; k < 8; k++) {
        float dh = hv - m[k];
        float v = (a[k] - lse_a) + 0.5f * lp[k] - 0.5f * __expf(lp[k]) * dh * dh;
        tv[k] = v;
        tmax = fmaxf(tmax, v);
    }
    float ts = 0.f;
#pragma unroll
    for (int k = 0; k < 8; k++) ts += __expf(tv[k] - tmax);
    const float Le_l = tmax + __logf(ts);

    // row scalar: (L_q - L_e) with -0.5*L*log2pi cancelled:
    float val = -0.5f * hv * hv - Le_l;
#pragma unroll
    for (int off = 16; off > 0; off >>= 1)
        val += __shfl_down_sync(0xffffffffu, val, off);
    if ((t & 31) == 0) red[t >> 5] = val;
    __syncthreads();
    if ((t & 63) == 0) g_row[n] = red[t >> 5] + red[(t >> 5) + 1];
}

// ---------------------------------------------------------------------------
// K3: fused decoder GEMM + mixture likelihood.
// Grid (16 d-tiles of 16, 64 row-blocks of 256 rows). 384 threads.
// Thread t -> (c = t/128, k = (t/16)&7, dd = t&15), owns column
//   col = c*2048 + k*256 + d0+dd of W_d, keeps its W column (64 f) in regs,
// loops over 16 row-groups of 16 rows: GEMM into 16 regs, exchange via smem,
// epilogue computes L_d items, accumulates block partial.
// ---------------------------------------------------------------------------
__global__ __launch_bounds__(384, 1) void k3_decoder(const float* __restrict__ x,
                                                     const float* __restrict__ Wd,
                                                     const float* __restrict__ bd) {
    __shared__ float hT[64 * 16];   // [l][r]
    __shared__ float xs[16 * 16];   // [r][dd]
    __shared__ float cs[384 * 16];  // [r][t] exchange
    __shared__ float red[12];

    const int t = threadIdx.x;
    const int d0 = blockIdx.x * 16;
    const int c = t >> 7;
    const int k = (t >> 4) & 7;
    const int dd = t & 15;
    const int col = c * 2048 + k * 256 + d0 + dd;

    float wreg[64];
#pragma unroll
    for (int l = 0; l < 64; l++) wreg[l] = Wd[l * 6144 + col];
    const float bdv = bd[col];

    float episum = 0.f;

    for (int g = 0; g < 16; g++) {
        const int row0 = blockIdx.y * 256 + g * 16;
        // stage h (transposed) and x slice
        for (int i = t; i < 1024; i += 384) {
            int r = i >> 6, l = i & 63;
            hT[l * 16 + r] = g_h[(row0 + r) * 64 + l];
        }
        for (int i = t; i < 256; i += 384) {
            int r = i >> 4, d = i & 15;
            xs[i] = x[((row0 + r) & 2047) * 256 + d0 + d];
        }
        __syncthreads();

        float acc[16];
#pragma unroll
        for (int r = 0; r < 16; r++) acc[r] = bdv;
#pragma unroll
        for (int l = 0; l < 64; l++) {
            const float w = wreg[l];
            float4 h0 = *(const float4*)&hT[l * 16 + 0];
            float4 h1 = *(const float4*)&hT[l * 16 + 4];
            float4 h2 = *(const float4*)&hT[l * 16 + 8];
            float4 h3 = *(const float4*)&hT[l * 16 + 12];
            acc[0]  = fmaf(w, h0.x, acc[0]);  acc[1]  = fmaf(w, h0.y, acc[1]);
            acc[2]  = fmaf(w, h0.z, acc[2]);  acc[3]  = fmaf(w, h0.w, acc[3]);
            acc[4]  = fmaf(w, h1.x, acc[4]);  acc[5]  = fmaf(w, h1.y, acc[5]);
            acc[6]  = fmaf(w, h1.z, acc[6]);  acc[7]  = fmaf(w, h1.w, acc[7]);
            acc[8]  = fmaf(w, h2.x, acc[8]);  acc[9]  = fmaf(w, h2.y, acc[9]);
            acc[10] = fmaf(w, h2.z, acc[10]); acc[11] = fmaf(w, h2.w, acc[11]);
            acc[12] = fmaf(w, h3.x, acc[12]); acc[13] = fmaf(w, h3.y, acc[13]);
            acc[14] = fmaf(w, h3.z, acc[14]); acc[15] = fmaf(w, h3.w, acc[15]);
        }
#pragma unroll
        for (int r = 0; r < 16; r++) cs[r * 384 + t] = acc[r];
        __syncthreads();

        if (t < 256) {
            const int r = t >> 4, d = t & 15;
            const float* base = &cs[r * 384 + d];
            float m[8], lp[8], a[8];
#pragma unroll
            for (int kk = 0; kk < 8; kk++) {
                m[kk]  = base[kk * 16];
                lp[kk] = base[128 + kk * 16];
                a[kk]  = base[256 + kk * 16];
            }
            const float xv = xs[r * 16 + d];
            float amax = a[0];
#pragma unroll
            for (int kk = 1; kk < 8; kk++) amax = fmaxf(amax, a[kk]);
            float se = 0.f;
#pragma unroll
            for (int kk = 0; kk < 8; kk++) se += __expf(a[kk] - amax);
            const float lse_a = amax + __logf(se);
            float tv[8];
            float tmax = -1e30f;
#pragma unroll
            for (int kk = 0; kk < 8; kk++) {
                float dx = xv - m[kk];
                float v = a[kk] + 0.5f * lp[kk] - 0.5f * __expf(lp[kk]) * dx * dx;
                tv[kk] = v;
                tmax = fmaxf(tmax, v);
            }
            float ts = 0.f;
#pragma unroll
            for (int kk = 0; kk < 8; kk++) ts += __expf(tv[kk] - tmax);
            episum += tmax + __logf(ts) - lse_a;
        }
        __syncthreads();
    }

    // block-reduce episum (threads >= 256 contribute 0)
    float v = episum;
#pragma unroll
    for (int off = 16; off > 0; off >>= 1)
        v += __shfl_down_sync(0xffffffffu, v, off);
    if ((t & 31) == 0) red[t >> 5] = v;
    __syncthreads();
    if (t == 0) {
        float s = 0.f;
#pragma unroll
        for (int w = 0; w < 12; w++) s += red[w];
        g_part[blockIdx.y * 16 + blockIdx.x] = s;
    }
}

// ---------------------------------------------------------------------------
// K4: deterministic final reduction (double accumulation, fixed tree order).
// out = -(S_d + S_row)/N + 0.5*D*log(2pi)
// ---------------------------------------------------------------------------
__global__ __launch_bounds__(256) void k4_final(float* __restrict__ out) {
    __shared__ double sd[256];
    const int t = threadIdx.x;
    double s = 0.0;
    for (int i = t; i < 1024; i += 256) s += (double)g_part[i];
    for (int i = t; i < NN; i += 256) s += (double)g_row[i];
    sd[t] = s;
    __syncthreads();
    for (int off = 128; off > 0; off >>= 1) {
        if (t < off) sd[t] += sd[t + off];
        __syncthreads();
    }
    if (t == 0)
        out[0] = (float)(-sd[0] / 16384.0 + 128.0 * 1.8378770664093453);
}

extern "C" void kernel_launch(void* const* d_in, const int* in_sizes, int n_in,
                              void* d_out, int out_size) {
    const float* x   = (const float*)d_in[0];
    const float* We  = (const float*)d_in[1];
    const float* be  = (const float*)d_in[2];
    const float* Wd  = (const float*)d_in[3];
    const float* bdv = (const float*)d_in[4];
    const float* ue  = (const float*)d_in[5];
    const float* rr  = (const float*)d_in[6];
    float* out = (float*)d_out;

    k1_gemm_e<<<dim3(24, 16), 256>>>(x, We, be);
    k2_encoder<<<4096, 256>>>(ue, rr);
    k3_decoder<<<dim3(16, 64), 384>>>(x, Wd, bdv);
    k4_final<<<1, 256>>>(out);
}

// round 2
// speedup vs baseline: 1.0399x; 1.0399x over previous
#include <cuda_runtime.h>

#define NN 16384
#define BATCH 2048

typedef unsigned long long ull;

// ---- packed fp32x2 helpers (FFMA2 path; ptxas never auto-generates this) ----
__device__ __forceinline__ ull pk2(float a, float b) {
    ull r; asm("mov.b64 %0, {%1,%2};" : "=l"(r) : "f"(a), "f"(b)); return r;
}
__device__ __forceinline__ void upk2(ull v, float& a, float& b) {
    asm("mov.b64 {%0,%1}, %2;" : "=f"(a), "=f"(b) : "l"(v));
}
__device__ __forceinline__ void fma2(ull& d, ull a, ull b) {
    asm("fma.rn.f32x2 %0, %1, %2, %0;" : "+l"(d) : "l"(a), "l"(b));
}

// Scratch (static __device__ — no allocations allowed)
__device__ float g_pred_e[BATCH * 1536];   // 12.6 MB
__device__ float g_h[NN * 64];             // 4 MB
__device__ float g_row[4096];              // encoder per-block partials
__device__ float g_part[1024];             // decoder block partials

// ---------------------------------------------------------------------------
// K1: pred_e = x @ W_e + b_e   (2048 x 1536, K=256)
// BM=128, BN=64, BK=16, 256 threads, 8x4 microtile, FFMA2 on row pairs
// ---------------------------------------------------------------------------
__global__ __launch_bounds__(256) void k1_gemm_e(const float* __restrict__ x,
                                                 const float* __restrict__ We,
                                                 const float* __restrict__ be) {
    __shared__ __align__(16) float As[16][128];
    __shared__ __align__(16) float Bs[16][64];
    const int bx = blockIdx.x;   // 0..23  (N)
    const int by = blockIdx.y;   // 0..15  (M)
    const int tid = threadIdx.x;
    const int tx = tid & 15;     // N dir
    const int ty = tid >> 4;     // M dir
    const int ar = tid >> 2;         // 0..63
    const int ac = (tid & 3) << 2;   // 0,4,8,12
    const int br = tid >> 4;         // 0..15
    const int bc = (tid & 15) << 2;  // 0..60

    ull acc2[4][4];   // [row_pair][col], each = rows (2ip, 2ip+1)
#pragma unroll
    for (int ip = 0; ip < 4; ip++)
#pragma unroll
        for (int j = 0; j < 4; j++) acc2[ip][j] = 0ull;

#pragma unroll 1
    for (int k0 = 0; k0 < 256; k0 += 16) {
        float4 a0 = *(const float4*)(x + (by * 128 + ar) * 256 + k0 + ac);
        float4 a1 = *(const float4*)(x + (by * 128 + ar + 64) * 256 + k0 + ac);
        As[ac + 0][ar] = a0.x; As[ac + 1][ar] = a0.y;
        As[ac + 2][ar] = a0.z; As[ac + 3][ar] = a0.w;
        As[ac + 0][ar + 64] = a1.x; As[ac + 1][ar + 64] = a1.y;
        As[ac + 2][ar + 64] = a1.z; As[ac + 3][ar + 64] = a1.w;
        float4 b0 = *(const float4*)(We + (k0 + br) * 1536 + bx * 64 + bc);
        *(float4*)&Bs[br][bc] = b0;
        __syncthreads();
#pragma unroll
        for (int kk = 0; kk < 16; kk++) {
            ulonglong2 Ap0 = *(const ulonglong2*)&As[kk][ty * 8];      // pairs (0,1),(2,3)
            ulonglong2 Ap1 = *(const ulonglong2*)&As[kk][ty * 8 + 4];  // pairs (4,5),(6,7)
            float4 bv = *(const float4*)&Bs[kk][tx * 4];
            ull b2[4] = {pk2(bv.x, bv.x), pk2(bv.y, bv.y), pk2(bv.z, bv.z), pk2(bv.w, bv.w)};
            ull ap[4] = {Ap0.x, Ap0.y, Ap1.x, Ap1.y};
#pragma unroll
            for (int ip = 0; ip < 4; ip++)
#pragma unroll
                for (int j = 0; j < 4; j++) fma2(acc2[ip][j], ap[ip], b2[j]);
        }
        __syncthreads();
    }
    float4 bias = *(const float4*)(be + bx * 64 + tx * 4);
#pragma unroll
    for (int ip = 0; ip < 4; ip++) {
        float lo[4], hi[4];
#pragma unroll
        for (int j = 0; j < 4; j++) upk2(acc2[ip][j], lo[j], hi[j]);
        float4 o0, o1;
        o0.x = lo[0] + bias.x; o0.y = lo[1] + bias.y; o0.z = lo[2] + bias.z; o0.w = lo[3] + bias.w;
        o1.x = hi[0] + bias.x; o1.y = hi[1] + bias.y; o1.z = hi[2] + bias.z; o1.w = hi[3] + bias.w;
        *(float4*)&g_pred_e[(by * 128 + ty * 8 + 2 * ip) * 1536 + bx * 64 + tx * 4] = o0;
        *(float4*)&g_pred_e[(by * 128 + ty * 8 + 2 * ip + 1) * 1536 + bx * 64 + tx * 4] = o1;
    }
}

// ---------------------------------------------------------------------------
// K2: encoder epilogue. One thread per (n, l). 4 rows per 256-thread block.
// Writes ONE partial per block (sum of L_q - L_e over its 4 rows).
// ---------------------------------------------------------------------------
__global__ __launch_bounds__(256) void k2_encoder(const float* __restrict__ u_e,
                                                  const float* __restrict__ r_in) {
    __shared__ float red[8];
    const int t = threadIdx.x;
    const int n = blockIdx.x * 4 + (t >> 6);
    const int l = t & 63;
    const int b = n & 2047;
    const float* pe = g_pred_e + b * 1536;

    float m[8], lp[8], a[8];
#pragma unroll
    for (int k = 0; k < 8; k++) {
        m[k]  = pe[k * 64 + l];
        lp[k] = pe[512 + k * 64 + l];
        a[k]  = pe[1024 + k * 64 + l];
    }
    float amax = a[0];
#pragma unroll
    for (int k = 1; k < 8; k++) amax = fmaxf(amax, a[k]);
    float e[8];
    float se = 0.f;
#pragma unroll
    for (int k = 0; k < 8; k++) { e[k] = __expf(a[k] - amax); se += e[k]; }
    const float lse_a = amax + __logf(se);
    const float inv_se = 1.f / se;

    const float rv = r_in[n * 64 + l];
    float cacc = 0.f;
    int idx = 0;
#pragma unroll
    for (int k = 0; k < 8; k++) {
        cacc += e[k] * inv_se;
        idx += (rv > cacc) ? 1 : 0;
    }
    if (idx > 7) idx = 7;
    float msel = m[0], lpsel = lp[0];
#pragma unroll
    for (int k = 1; k < 8; k++)
        if (idx == k) { msel = m[k]; lpsel = lp[k]; }
    const float hv = fmaf(__expf(-0.5f * lpsel), u_e[n * 64 + l], msel);
    g_h[n * 64 + l] = hv;

    float tv[8];
    float tmax = -1e30f;
#pragma unroll
    for (int k = 0; k < 8; k++) {
        float dh = hv - m[k];
        float v = (a[k] - lse_a) + 0.5f * lp[k] - 0.5f * __expf(lp[k]) * dh * dh;
        tv[k] = v;
        tmax = fmaxf(tmax, v);
    }
    float ts = 0.f;
#pragma unroll
    for (int k = 0; k < 8; k++) ts += __expf(tv[k] - tmax);
    const float Le_l = tmax + __logf(ts);

    float val = -0.5f * hv * hv - Le_l;
#pragma unroll
    for (int off = 16; off > 0; off >>= 1)
        val += __shfl_down_sync(0xffffffffu, val, off);
    if ((t & 31) == 0) red[t >> 5] = val;
    __syncthreads();
    if (t == 0) {
        float s = 0.f;
#pragma unroll
        for (int w = 0; w < 8; w++) s += red[w];
        g_row[blockIdx.x] = s;
    }
}

// ---------------------------------------------------------------------------
// K3: fused decoder GEMM + mixture likelihood. FFMA2 on row pairs.
// Grid (16 d-tiles of 16, 64 row-blocks of 256 rows). 384 threads.
// Thread t owns one W_d column (64 floats in regs); per group of 16 rows:
// GEMM into 8 packed accumulators, exchange via smem, epilogue L_d.
// ---------------------------------------------------------------------------
__global__ __launch_bounds__(384, 1) void k3_decoder(const float* __restrict__ x,
                                                     const float* __restrict__ Wd,
                                                     const float* __restrict__ bd) {
    __shared__ __align__(16) float hT[64 * 16];   // [l][r]
    __shared__ float xs[16 * 16];   // [r][dd]
    __shared__ float cs[384 * 16];  // [r][t] exchange
    __shared__ float red[12];

    const int t = threadIdx.x;
    const int d0 = blockIdx.x * 16;
    const int c = t >> 7;
    const int k = (t >> 4) & 7;
    const int dd = t & 15;
    const int col = c * 2048 + k * 256 + d0 + dd;

    float wreg[64];
#pragma unroll
    for (int l = 0; l < 64; l++) wreg[l] = Wd[l * 6144 + col];
    const float bdv = bd[col];
    const ull binit = pk2(bdv, bdv);

    float episum = 0.f;

#pragma unroll 1
    for (int g = 0; g < 16; g++) {
        const int row0 = blockIdx.y * 256 + g * 16;
        for (int i = t; i < 1024; i += 384) {
            int r = i >> 6, l = i & 63;
            hT[l * 16 + r] = g_h[(row0 + r) * 64 + l];
        }
        for (int i = t; i < 256; i += 384) {
            int r = i >> 4, d = i & 15;
            xs[i] = x[((row0 + r) & 2047) * 256 + d0 + d];
        }
        __syncthreads();

        ull acc2[8];   // row pairs (0,1)..(14,15)
#pragma unroll
        for (int j = 0; j < 8; j++) acc2[j] = binit;
#pragma unroll
        for (int l = 0; l < 64; l++) {
            const ull w2 = pk2(wreg[l], wreg[l]);
            const ulonglong2* hp = (const ulonglong2*)(hT + l * 16);
            ulonglong2 hA = hp[0];
            ulonglong2 hB = hp[1];
            fma2(acc2[0], w2, hA.x); fma2(acc2[1], w2, hA.y);
            fma2(acc2[2], w2, hB.x); fma2(acc2[3], w2, hB.y);
            hA = hp[2]; hB = hp[3];
            fma2(acc2[4], w2, hA.x); fma2(acc2[5], w2, hA.y);
            fma2(acc2[6], w2, hB.x); fma2(acc2[7], w2, hB.y);
        }
#pragma unroll
        for (int j = 0; j < 8; j++) {
            float lo, hi;
            upk2(acc2[j], lo, hi);
            cs[(2 * j) * 384 + t] = lo;
            cs[(2 * j + 1) * 384 + t] = hi;
        }
        __syncthreads();

        if (t < 256) {
            const int r = t >> 4, d = t & 15;
            const float* base = &cs[r * 384 + d];
            float m[8], lp[8], a[8];
#pragma unroll
            for (int kk = 0; kk < 8; kk++) {
                m[kk]  = base[kk * 16];
                lp[kk] = base[128 + kk * 16];
                a[kk]  = base[256 + kk * 16];
            }
            const float xv = xs[r * 16 + d];
            float amax = a[0];
#pragma unroll
            for (int kk = 1; kk < 8; kk++) amax = fmaxf(amax, a[kk]);
            float se = 0.f;
#pragma unroll
            for (int kk = 0; kk < 8; kk++) se += __expf(a[kk] - amax);
            const float lse_a = amax + __logf(se);
            float tv[8];
            float tmax = -1e30f;
#pragma unroll
            for (int kk = 0; kk < 8; kk++) {
                float dx = xv - m[kk];
                float v = a[kk] + 0.5f * lp[kk] - 0.5f * __expf(lp[kk]) * dx * dx;
                tv[kk] = v;
                tmax = fmaxf(tmax, v);
            }
            float ts = 0.f;
#pragma unroll
            for (int kk = 0; kk < 8; kk++) ts += __expf(tv[kk] - tmax);
            episum += tmax + __logf(ts) - lse_a;
        }
        __syncthreads();
    }

    float v = episum;
#pragma unroll
    for (int off = 16; off > 0; off >>= 1)
        v += __shfl_down_sync(0xffffffffu, v, off);
    if ((t & 31) == 0) red[t >> 5] = v;
    __syncthreads();
    if (t == 0) {
        float s = 0.f;
#pragma unroll
        for (int w = 0; w < 12; w++) s += red[w];
        g_part[blockIdx.y * 16 + blockIdx.x] = s;
    }
}

// ---------------------------------------------------------------------------
// K4: deterministic final reduction (double accumulation, fixed tree order).
// ---------------------------------------------------------------------------
__global__ __launch_bounds__(512) void k4_final(float* __restrict__ out) {
    __shared__ double sd[512];
    const int t = threadIdx.x;
    double s = 0.0;
    for (int i = t; i < 1024; i += 512) s += (double)g_part[i];
    for (int i = t; i < 4096; i += 512) s += (double)g_row[i];
    sd[t] = s;
    __syncthreads();
    for (int off = 256; off > 0; off >>= 1) {
        if (t < off) sd[t] += sd[t + off];
        __syncthreads();
    }
    if (t == 0)
        out[0] = (float)(-sd[0] / 16384.0 + 128.0 * 1.8378770664093453);
}

extern "C" void kernel_launch(void* const* d_in, const int* in_sizes, int n_in,
                              void* d_out, int out_size) {
    const float* x   = (const float*)d_in[0];
    const float* We  = (const float*)d_in[1];
    const float* be  = (const float*)d_in[2];
    const float* Wd  = (const float*)d_in[3];
    const float* bdv = (const float*)d_in[4];
    const float* ue  = (const float*)d_in[5];
    const float* rr  = (const float*)d_in[6];
    float* out = (float*)d_out;

    k1_gemm_e<<<dim3(24, 16), 256>>>(x, We, be);
    k2_encoder<<<4096, 256>>>(ue, rr);
    k3_decoder<<<dim3(16, 64), 384>>>(x, Wd, bdv);
    k4_final<<<1, 512>>>(out);
}

// round 6
// speedup vs baseline: 3.7896x; 3.6442x over previous
#include <cuda_runtime.h>
#include <cuda_fp16.h>
#include <cstdint>

#define NN 16384
#define BATCH 2048

typedef unsigned long long ull;

// ---- packed fp32x2 helpers (k1) ----
__device__ __forceinline__ ull pk2(float a, float b) {
    ull r; asm("mov.b64 %0, {%1,%2};" : "=l"(r) : "f"(a), "f"(b)); return r;
}
__device__ __forceinline__ void upk2(ull v, float& a, float& b) {
    asm("mov.b64 {%0,%1}, %2;" : "=f"(a), "=f"(b) : "l"(v));
}
__device__ __forceinline__ void fma2(ull& d, ull a, ull b) {
    asm("fma.rn.f32x2 %0, %1, %2, %0;" : "+l"(d) : "l"(a), "l"(b));
}

__device__ __forceinline__ uint32_t smem_u32(const void* p) {
    uint32_t a;
    asm("{ .reg .u64 t; cvta.to.shared.u64 t, %1; cvt.u32.u64 %0, t; }" : "=r"(a) : "l"(p));
    return a;
}

// Scratch
__device__ float g_pred_e[BATCH * 1536];
__device__ __align__(16) unsigned short g_h_h[NN * 64];   // h in fp16
__device__ float g_row[4096];
__device__ float g_part[1024];

// ---------------------------------------------------------------------------
// K1: pred_e = x @ W_e + b_e   (2048 x 1536, K=256)  fp32 FFMA2 (unchanged)
// ---------------------------------------------------------------------------
__global__ __launch_bounds__(256) void k1_gemm_e(const float* __restrict__ x,
                                                 const float* __restrict__ We,
                                                 const float* __restrict__ be) {
    __shared__ __align__(16) float As[16][128];
    __shared__ __align__(16) float Bs[16][64];
    const int bx = blockIdx.x;
    const int by = blockIdx.y;
    const int tid = threadIdx.x;
    const int tx = tid & 15;
    const int ty = tid >> 4;
    const int ar = tid >> 2;
    const int ac = (tid & 3) << 2;
    const int br = tid >> 4;
    const int bc = (tid & 15) << 2;

    ull acc2[4][4];
#pragma unroll
    for (int ip = 0; ip < 4; ip++)
#pragma unroll
        for (int j = 0; j < 4; j++) acc2[ip][j] = 0ull;

#pragma unroll 1
    for (int k0 = 0; k0 < 256; k0 += 16) {
        float4 a0 = *(const float4*)(x + (by * 128 + ar) * 256 + k0 + ac);
        float4 a1 = *(const float4*)(x + (by * 128 + ar + 64) * 256 + k0 + ac);
        As[ac + 0][ar] = a0.x; As[ac + 1][ar] = a0.y;
        As[ac + 2][ar] = a0.z; As[ac + 3][ar] = a0.w;
        As[ac + 0][ar + 64] = a1.x; As[ac + 1][ar + 64] = a1.y;
        As[ac + 2][ar + 64] = a1.z; As[ac + 3][ar + 64] = a1.w;
        float4 b0 = *(const float4*)(We + (k0 + br) * 1536 + bx * 64 + bc);
        *(float4*)&Bs[br][bc] = b0;
        __syncthreads();
#pragma unroll
        for (int kk = 0; kk < 16; kk++) {
            ulonglong2 Ap0 = *(const ulonglong2*)&As[kk][ty * 8];
            ulonglong2 Ap1 = *(const ulonglong2*)&As[kk][ty * 8 + 4];
            float4 bv = *(const float4*)&Bs[kk][tx * 4];
            ull b2[4] = {pk2(bv.x, bv.x), pk2(bv.y, bv.y), pk2(bv.z, bv.z), pk2(bv.w, bv.w)};
            ull ap[4] = {Ap0.x, Ap0.y, Ap1.x, Ap1.y};
#pragma unroll
            for (int ip = 0; ip < 4; ip++)
#pragma unroll
                for (int j = 0; j < 4; j++) fma2(acc2[ip][j], ap[ip], b2[j]);
        }
        __syncthreads();
    }
    float4 bias = *(const float4*)(be + bx * 64 + tx * 4);
#pragma unroll
    for (int ip = 0; ip < 4; ip++) {
        float lo[4], hi[4];
#pragma unroll
        for (int j = 0; j < 4; j++) upk2(acc2[ip][j], lo[j], hi[j]);
        float4 o0, o1;
        o0.x = lo[0] + bias.x; o0.y = lo[1] + bias.y; o0.z = lo[2] + bias.z; o0.w = lo[3] + bias.w;
        o1.x = hi[0] + bias.x; o1.y = hi[1] + bias.y; o1.z = hi[2] + bias.z; o1.w = hi[3] + bias.w;
        *(float4*)&g_pred_e[(by * 128 + ty * 8 + 2 * ip) * 1536 + bx * 64 + tx * 4] = o0;
        *(float4*)&g_pred_e[(by * 128 + ty * 8 + 2 * ip + 1) * 1536 + bx * 64 + tx * 4] = o1;
    }
}

// ---------------------------------------------------------------------------
// K2: encoder epilogue; writes h as fp16.
// ---------------------------------------------------------------------------
__global__ __launch_bounds__(256) void k2_encoder(const float* __restrict__ u_e,
                                                  const float* __restrict__ r_in) {
    __shared__ float red[8];
    const int t = threadIdx.x;
    const int n = blockIdx.x * 4 + (t >> 6);
    const int l = t & 63;
    const int b = n & 2047;
    const float* pe = g_pred_e + b * 1536;

    float m[8], lp[8], a[8];
#pragma unroll
    for (int k = 0; k < 8; k++) {
        m[k]  = pe[k * 64 + l];
        lp[k] = pe[512 + k * 64 + l];
        a[k]  = pe[1024 + k * 64 + l];
    }
    float amax = a[0];
#pragma unroll
    for (int k = 1; k < 8; k++) amax = fmaxf(amax, a[k]);
    float e[8];
    float se = 0.f;
#pragma unroll
    for (int k = 0; k < 8; k++) { e[k] = __expf(a[k] - amax); se += e[k]; }
    const float lse_a = amax + __logf(se);
    const float inv_se = 1.f / se;

    const float rv = r_in[n * 64 + l];
    float cacc = 0.f;
    int idx = 0;
#pragma unroll
    for (int k = 0; k < 8; k++) {
        cacc += e[k] * inv_se;
        idx += (rv > cacc) ? 1 : 0;
    }
    if (idx > 7) idx = 7;
    float msel = m[0], lpsel = lp[0];
#pragma unroll
    for (int k = 1; k < 8; k++)
        if (idx == k) { msel = m[k]; lpsel = lp[k]; }
    const float hv = fmaf(__expf(-0.5f * lpsel), u_e[n * 64 + l], msel);
    ((__half*)g_h_h)[n * 64 + l] = __float2half_rn(hv);

    float tv[8];
    float tmax = -1e30f;
#pragma unroll
    for (int k = 0; k < 8; k++) {
        float dh = hv - m[k];
        float v = (a[k] - lse_a) + 0.5f * lp[k] - 0.5f * __expf(lp[k]) * dh * dh;
        tv[k] = v;
        tmax = fmaxf(tmax, v);
    }
    float ts = 0.f;
#pragma unroll
    for (int k = 0; k < 8; k++) ts += __expf(tv[k] - tmax);
    const float Le_l = tmax + __logf(ts);

    float val = -0.5f * hv * hv - Le_l;
#pragma unroll
    for (int off = 16; off > 0; off >>= 1)
        val += __shfl_down_sync(0xffffffffu, val, off);
    if ((t & 31) == 0) red[t >> 5] = val;
    __syncthreads();
    if (t == 0) {
        float s = 0.f;
#pragma unroll
        for (int w = 0; w < 8; w++) s += red[w];
        g_row[blockIdx.x] = s;
    }
}

// ---------------------------------------------------------------------------
// K3: HMMA (mma.sync m16n8k16 fp16->fp32) decoder GEMM + register-resident
// mixture-likelihood epilogue.
// Grid (16 d-chunks, 64 row-blocks of 256). 256 threads = 8 warps (4 row x 2 col).
// smem: WdT [384 cols][88 k] fp16 (k 0..63 = Wd, 64 = bias, 65..79 = 0),
//       h   [64 rows][88 k] fp16 (k64 = 1.0), xs [64][16] f32.
// K padded to 80 -> bias folded exactly into the GEMM.
// ---------------------------------------------------------------------------
#define PITCH 88
#define OFF_W 0
#define OFF_H 67584
#define OFF_X 78848
#define K3_SMEM 82944

__global__ __launch_bounds__(256) void k3_decoder_m(const float* __restrict__ x,
                                                    const float* __restrict__ Wd,
                                                    const float* __restrict__ bd) {
    extern __shared__ char smem[];
    __shared__ float red[8];
    const uint32_t sb = smem_u32(smem);
    const int t = threadIdx.x;
    const int lane = t & 31;
    const int wid = t >> 5;
    const int rwarp = wid & 3;
    const int cwarp = wid >> 2;
    const int d0 = blockIdx.x * 16;

    __half* wsm = (__half*)(smem + OFF_W);
    __half* hsm = (__half*)(smem + OFF_H);
    float* xsf = (float*)(smem + OFF_X);

    // Stage WdT: col c = tile*128 + comp*16 + dd  ->  gmem col tile*2048+comp*256+d0+dd
    for (int s = 0; s < 96; s++) {
        int idx = t + 256 * s;
        int k = idx / 384;
        int c = idx - k * 384;
        int cg = (c >> 7) * 2048 + ((c >> 4) & 7) * 256 + d0 + (c & 15);
        wsm[c * PITCH + k] = __float2half_rn(Wd[k * 6144 + cg]);
    }
    // bias row (k=64) + zero pad (65..79)
    for (int i = t; i < 384 * 16; i += 256) {
        int c = i >> 4, kk = 64 + (i & 15);
        float v = 0.f;
        if (kk == 64) {
            int cg = (c >> 7) * 2048 + ((c >> 4) & 7) * 256 + d0 + (c & 15);
            v = bd[cg];
        }
        wsm[c * PITCH + kk] = __float2half_rn(v);
    }
    // h pad (constant across iters)
    for (int i = t; i < 64 * 16; i += 256) {
        int r = i >> 4, kk = 64 + (i & 15);
        hsm[r * PITCH + kk] = (kk == 64) ? __float2half_rn(1.f) : __float2half_rn(0.f);
    }

    // ldmatrix base addresses
    const uint32_t a_base = sb + OFF_H +
        (uint32_t)(((rwarp * 16 + (lane & 15)) * PITCH + ((lane >> 4) << 3)) * 2);
    uint32_t b_base;
    {
        int q = lane >> 3;
        int col0 = ((q >= 2) ? 16 : 0) + (lane & 7) + 8 * cwarp;
        b_base = sb + OFF_W + (uint32_t)((col0 * PITCH + (q & 1) * 8) * 2);
    }

    const int groupr = lane >> 2, qr = lane & 3;
    float episum = 0.f;

#pragma unroll 1
    for (int it = 0; it < 4; it++) {
        const int row0 = blockIdx.y * 256 + it * 64;
        __syncthreads();
        // stage h rows (64 x 64 halfs, vectorized 16B)
        {
            const uint4* src = (const uint4*)g_h_h;
#pragma unroll
            for (int s = 0; s < 2; s++) {
                int idx = t + 256 * s;
                int r = idx >> 3, seg = idx & 7;
                uint4 v = src[(row0 + r) * 8 + seg];
                *(uint4*)&hsm[r * PITCH + seg * 8] = v;
            }
        }
        // stage x slice
#pragma unroll
        for (int s = 0; s < 4; s++) {
            int idx = t + 256 * s;
            int r = idx >> 4, dd = idx & 15;
            xsf[idx] = x[((row0 + r) & 2047) * 256 + d0 + dd];
        }
        __syncthreads();

        float acc[24][4];
#pragma unroll
        for (int j = 0; j < 24; j++)
#pragma unroll
            for (int e = 0; e < 4; e++) acc[j][e] = 0.f;

#pragma unroll
        for (int ks = 0; ks < 5; ks++) {
            uint32_t a0, a1, a2, a3;
            asm volatile("ldmatrix.sync.aligned.m8n8.x4.shared.b16 {%0,%1,%2,%3}, [%4];"
                         : "=r"(a0), "=r"(a1), "=r"(a2), "=r"(a3)
                         : "r"(a_base + ks * 32));
#pragma unroll
            for (int p = 0; p < 12; p++) {
                uint32_t b0, b1, b2, b3;
                asm volatile("ldmatrix.sync.aligned.m8n8.x4.shared.b16 {%0,%1,%2,%3}, [%4];"
                             : "=r"(b0), "=r"(b1), "=r"(b2), "=r"(b3)
                             : "r"(b_base + p * (32 * PITCH * 2) + ks * 32));
                asm volatile("mma.sync.aligned.m16n8k16.row.col.f32.f16.f16.f32 "
                             "{%0,%1,%2,%3}, {%4,%5,%6,%7}, {%8,%9}, {%0,%1,%2,%3};"
                             : "+f"(acc[2 * p][0]), "+f"(acc[2 * p][1]),
                               "+f"(acc[2 * p][2]), "+f"(acc[2 * p][3])
                             : "r"(a0), "r"(a1), "r"(a2), "r"(a3), "r"(b0), "r"(b1));
                asm volatile("mma.sync.aligned.m16n8k16.row.col.f32.f16.f16.f32 "
                             "{%0,%1,%2,%3}, {%4,%5,%6,%7}, {%8,%9}, {%0,%1,%2,%3};"
                             : "+f"(acc[2 * p + 1][0]), "+f"(acc[2 * p + 1][1]),
                               "+f"(acc[2 * p + 1][2]), "+f"(acc[2 * p + 1][3])
                             : "r"(a0), "r"(a1), "r"(a2), "r"(a3), "r"(b2), "r"(b3));
            }
        }

        // register-resident epilogue: 4 items per thread
#pragma unroll
        for (int hh = 0; hh < 2; hh++) {
            const int r_loc = rwarp * 16 + groupr + 8 * hh;
#pragma unroll
            for (int par = 0; par < 2; par++) {
                const int e = 2 * hh + par;
                const int dd = 8 * cwarp + 2 * qr + par;
                const float xv = xsf[r_loc * 16 + dd];
                float a8[8];
                float amax = -1e30f;
#pragma unroll
                for (int k = 0; k < 8; k++) {
                    a8[k] = acc[16 + k][e];
                    amax = fmaxf(amax, a8[k]);
                }
                float se = 0.f;
#pragma unroll
                for (int k = 0; k < 8; k++) se += __expf(a8[k] - amax);
                const float lse_a = amax + __logf(se);
                float tvv[8];
                float tmax = -1e30f;
#pragma unroll
                for (int k = 0; k < 8; k++) {
                    float lpv = acc[8 + k][e];
                    float dx = xv - acc[k][e];
                    float v = a8[k] + 0.5f * lpv - 0.5f * __expf(lpv) * dx * dx;
                    tvv[k] = v;
                    tmax = fmaxf(tmax, v);
                }
                float ts = 0.f;
#pragma unroll
                for (int k = 0; k < 8; k++) ts += __expf(tvv[k] - tmax);
                episum += tmax + __logf(ts) - lse_a;
            }
        }
    }

    float v = episum;
#pragma unroll
    for (int off = 16; off > 0; off >>= 1)
        v += __shfl_down_sync(0xffffffffu, v, off);
    if (lane == 0) red[wid] = v;
    __syncthreads();
    if (t == 0) {
        float s = 0.f;
#pragma unroll
        for (int w = 0; w < 8; w++) s += red[w];
        g_part[blockIdx.y * 16 + blockIdx.x] = s;
    }
}

// ---------------------------------------------------------------------------
// K4: deterministic final reduction.
// ---------------------------------------------------------------------------
__global__ __launch_bounds__(512) void k4_final(float* __restrict__ out) {
    __shared__ double sd[512];
    const int t = threadIdx.x;
    double s = 0.0;
    for (int i = t; i < 1024; i += 512) s += (double)g_part[i];
    for (int i = t; i < 4096; i += 512) s += (double)g_row[i];
    sd[t] = s;
    __syncthreads();
    for (int off = 256; off > 0; off >>= 1) {
        if (t < off) sd[t] += sd[t + off];
        __syncthreads();
    }
    if (t == 0)
        out[0] = (float)(-sd[0] / 16384.0 + 128.0 * 1.8378770664093453);
}

extern "C" void kernel_launch(void* const* d_in, const int* in_sizes, int n_in,
                              void* d_out, int out_size) {
    const float* x   = (const float*)d_in[0];
    const float* We  = (const float*)d_in[1];
    const float* be  = (const float*)d_in[2];
    const float* Wd  = (const float*)d_in[3];
    const float* bdv = (const float*)d_in[4];
    const float* ue  = (const float*)d_in[5];
    const float* rr  = (const float*)d_in[6];
    float* out = (float*)d_out;

    static int smem_set = 0;
    if (!smem_set) {
        cudaFuncSetAttribute(k3_decoder_m, cudaFuncAttributeMaxDynamicSharedMemorySize, K3_SMEM);
        smem_set = 1;
    }

    k1_gemm_e<<<dim3(24, 16), 256>>>(x, We, be);
    k2_encoder<<<4096, 256>>>(ue, rr);
    k3_decoder_m<<<dim3(16, 64), 256, K3_SMEM>>>(x, Wd, bdv);
    k4_final<<<1, 512>>>(out);
}

// round 9
// speedup vs baseline: 4.1911x; 1.1060x over previous
#include <cuda_runtime.h>
#include <cuda_fp16.h>
#include <cstdint>

#define NN 16384
#define BATCH 2048

typedef unsigned long long ull;

__device__ __forceinline__ uint32_t smem_u32(const void* p) {
    uint32_t a;
    asm("{ .reg .u64 t; cvta.to.shared.u64 t, %1; cvt.u32.u64 %0, t; }" : "=r"(a) : "l"(p));
    return a;
}

// Scratch
__device__ float g_pred_e[BATCH * 1536];
__device__ __align__(16) unsigned short g_h_h[NN * 64];        // h fp16
__device__ __align__(16) unsigned short g_x16[BATCH * 768];    // [x_hi | x_lo | x_hi]
__device__ __align__(16) unsigned short g_w16[1536 * 768];     // per col: [W_hi ; W_hi ; W_lo]
__device__ float g_row[4096];
__device__ float g_part[1024];
__device__ unsigned int g_done;

// ---------------------------------------------------------------------------
// K0: build split-fp16 operands for the encoder GEMM; reset completion ctr.
// blocks 0..2047: x part (coalesced). blocks 2048..2431: W transpose part.
// ---------------------------------------------------------------------------
__global__ __launch_bounds__(256) void k0_prep(const float* __restrict__ x,
                                               const float* __restrict__ We) {
    __shared__ float tile[32][33];
    const int b = blockIdx.x;
    if (b < 2048) {
        int i = b * 256 + threadIdx.x;
        if (i == 0) g_done = 0;
        int r = i >> 8, c = i & 255;
        float v = x[i];
        __half hi = __float2half_rn(v);
        __half lo = __float2half_rn(v - __half2float(hi));
        g_x16[r * 768 + c]       = __half_as_ushort(hi);
        g_x16[r * 768 + 256 + c] = __half_as_ushort(lo);
        g_x16[r * 768 + 512 + c] = __half_as_ushort(hi);
    } else {
        int wb = b - 2048;           // 0..383
        int bk = wb & 7, bn = wb >> 3;
        int tx = threadIdx.x & 31, ty = threadIdx.x >> 5;
#pragma unroll
        for (int s = 0; s < 4; s++)
            tile[ty + 8 * s][tx] = We[(bk * 32 + ty + 8 * s) * 1536 + bn * 32 + tx];
        __syncthreads();
#pragma unroll
        for (int s = 0; s < 4; s++) {
            int nl = ty + 8 * s;
            float v = tile[tx][nl];
            __half hi = __float2half_rn(v);
            __half lo = __float2half_rn(v - __half2float(hi));
            unsigned short* gw = g_w16 + (bn * 32 + nl) * 768 + bk * 32 + tx;
            gw[0]   = __half_as_ushort(hi);
            gw[256] = __half_as_ushort(hi);
            gw[512] = __half_as_ushort(lo);
        }
    }
}

// ---------------------------------------------------------------------------
// K1: encoder GEMM on HMMA. pred_e[2048x1536] = A[2048x768] * B[768x1536]+be
// Tile 128x128, grid (12,16), 256 thr = 8 warps (4 row x 2 col).
// ---------------------------------------------------------------------------
#define K1P 72
__global__ __launch_bounds__(256) void k1_hmma(const float* __restrict__ be) {
    __shared__ __align__(16) __half Asm[128 * K1P];
    __shared__ __align__(16) __half Bsm[128 * K1P];
    const int t = threadIdx.x, lane = t & 31, wid = t >> 5;
    const int rwarp = wid & 3, cwarp = wid >> 2;
    const int rows0 = blockIdx.y * 128, cols0 = blockIdx.x * 128;

    float acc[2][4][2][4];
#pragma unroll
    for (int mt = 0; mt < 2; mt++)
#pragma unroll
        for (int p = 0; p < 4; p++)
#pragma unroll
            for (int pr = 0; pr < 2; pr++)
#pragma unroll
                for (int e = 0; e < 4; e++) acc[mt][p][pr][e] = 0.f;

    const uint32_t a_base = smem_u32(Asm) +
        (uint32_t)(((rwarp * 32 + (lane & 15)) * K1P + ((lane >> 4) << 3)) * 2);
    uint32_t b_base;
    {
        int q = lane >> 3;
        int col0 = ((q >= 2) ? 16 : 0) + (lane & 7) + 8 * cwarp;
        b_base = smem_u32(Bsm) + (uint32_t)((col0 * K1P + ((q & 1) << 3)) * 2);
    }

    const __half* gx = (const __half*)g_x16;
    const __half* gw = (const __half*)g_w16;

#pragma unroll 1
    for (int ks = 0; ks < 12; ks++) {
        __syncthreads();
#pragma unroll
        for (int s = 0; s < 4; s++) {
            int idx = t + 256 * s;
            int r = idx >> 3, seg = idx & 7;
            *(uint4*)(Asm + r * K1P + seg * 8) =
                *(const uint4*)(gx + (rows0 + r) * 768 + ks * 64 + seg * 8);
            *(uint4*)(Bsm + r * K1P + seg * 8) =
                *(const uint4*)(gw + (cols0 + r) * 768 + ks * 64 + seg * 8);
        }
        __syncthreads();
#pragma unroll
        for (int kk = 0; kk < 4; kk++) {
            uint32_t a[2][4];
#pragma unroll
            for (int mt = 0; mt < 2; mt++)
                asm volatile("ldmatrix.sync.aligned.m8n8.x4.shared.b16 {%0,%1,%2,%3}, [%4];"
                             : "=r"(a[mt][0]), "=r"(a[mt][1]), "=r"(a[mt][2]), "=r"(a[mt][3])
                             : "r"(a_base + mt * (16 * K1P * 2) + kk * 32));
#pragma unroll
            for (int p = 0; p < 4; p++) {
                uint32_t b0, b1, b2, b3;
                asm volatile("ldmatrix.sync.aligned.m8n8.x4.shared.b16 {%0,%1,%2,%3}, [%4];"
                             : "=r"(b0), "=r"(b1), "=r"(b2), "=r"(b3)
                             : "r"(b_base + p * (32 * K1P * 2) + kk * 32));
#pragma unroll
                for (int mt = 0; mt < 2; mt++) {
                    asm volatile("mma.sync.aligned.m16n8k16.row.col.f32.f16.f16.f32 "
                                 "{%0,%1,%2,%3}, {%4,%5,%6,%7}, {%8,%9}, {%0,%1,%2,%3};"
                                 : "+f"(acc[mt][p][0][0]), "+f"(acc[mt][p][0][1]),
                                   "+f"(acc[mt][p][0][2]), "+f"(acc[mt][p][0][3])
                                 : "r"(a[mt][0]), "r"(a[mt][1]), "r"(a[mt][2]), "r"(a[mt][3]),
                                   "r"(b0), "r"(b1));
                    asm volatile("mma.sync.aligned.m16n8k16.row.col.f32.f16.f16.f32 "
                                 "{%0,%1,%2,%3}, {%4,%5,%6,%7}, {%8,%9}, {%0,%1,%2,%3};"
                                 : "+f"(acc[mt][p][1][0]), "+f"(acc[mt][p][1][1]),
                                   "+f"(acc[mt][p][1][2]), "+f"(acc[mt][p][1][3])
                                 : "r"(a[mt][0]), "r"(a[mt][1]), "r"(a[mt][2]), "r"(a[mt][3]),
                                   "r"(b2), "r"(b3));
                }
            }
        }
    }

    const int groupr = lane >> 2, qr = lane & 3;
#pragma unroll
    for (int p = 0; p < 4; p++)
#pragma unroll
        for (int pr = 0; pr < 2; pr++) {
            const int cb = p * 32 + pr * 16 + 8 * cwarp + 2 * qr;
            const float2 bias = *(const float2*)(be + cols0 + cb);
#pragma unroll
            for (int mt = 0; mt < 2; mt++) {
                const int r0 = rwarp * 32 + mt * 16 + groupr;
                float2 o0 = {acc[mt][p][pr][0] + bias.x, acc[mt][p][pr][1] + bias.y};
                float2 o1 = {acc[mt][p][pr][2] + bias.x, acc[mt][p][pr][3] + bias.y};
                *(float2*)&g_pred_e[(rows0 + r0) * 1536 + cols0 + cb] = o0;
                *(float2*)&g_pred_e[(rows0 + r0 + 8) * 1536 + cols0 + cb] = o1;
            }
        }
}

// ---------------------------------------------------------------------------
// K2: encoder epilogue; writes h as fp16. (unchanged)
// ---------------------------------------------------------------------------
__global__ __launch_bounds__(256) void k2_encoder(const float* __restrict__ u_e,
                                                  const float* __restrict__ r_in) {
    __shared__ float red[8];
    const int t = threadIdx.x;
    const int n = blockIdx.x * 4 + (t >> 6);
    const int l = t & 63;
    const int b = n & 2047;
    const float* pe = g_pred_e + b * 1536;

    float m[8], lp[8], a[8];
#pragma unroll
    for (int k = 0; k < 8; k++) {
        m[k]  = pe[k * 64 + l];
        lp[k] = pe[512 + k * 64 + l];
        a[k]  = pe[1024 + k * 64 + l];
    }
    float amax = a[0];
#pragma unroll
    for (int k = 1; k < 8; k++) amax = fmaxf(amax, a[k]);
    float e[8];
    float se = 0.f;
#pragma unroll
    for (int k = 0; k < 8; k++) { e[k] = __expf(a[k] - amax); se += e[k]; }
    const float lse_a = amax + __logf(se);
    const float inv_se = 1.f / se;

    const float rv = r_in[n * 64 + l];
    float cacc = 0.f;
    int idx = 0;
#pragma unroll
    for (int k = 0; k < 8; k++) {
        cacc += e[k] * inv_se;
        idx += (rv > cacc) ? 1 : 0;
    }
    if (idx > 7) idx = 7;
    float msel = m[0], lpsel = lp[0];
#pragma unroll
    for (int k = 1; k < 8; k++)
        if (idx == k) { msel = m[k]; lpsel = lp[k]; }
    const float hv = fmaf(__expf(-0.5f * lpsel), u_e[n * 64 + l], msel);
    ((__half*)g_h_h)[n * 64 + l] = __float2half_rn(hv);

    float tv[8];
    float tmax = -1e30f;
#pragma unroll
    for (int k = 0; k < 8; k++) {
        float dh = hv - m[k];
        float v = (a[k] - lse_a) + 0.5f * lp[k] - 0.5f * __expf(lp[k]) * dh * dh;
        tv[k] = v;
        tmax = fmaxf(tmax, v);
    }
    float ts = 0.f;
#pragma unroll
    for (int k = 0; k < 8; k++) ts += __expf(tv[k] - tmax);
    const float Le_l = tmax + __logf(ts);

    float val = -0.5f * hv * hv - Le_l;
#pragma unroll
    for (int off = 16; off > 0; off >>= 1)
        val += __shfl_down_sync(0xffffffffu, val, off);
    if ((t & 31) == 0) red[t >> 5] = val;
    __syncthreads();
    if (t == 0) {
        float s = 0.f;
#pragma unroll
        for (int w = 0; w < 8; w++) s += red[w];
        g_row[blockIdx.x] = s;
    }
}

// ---------------------------------------------------------------------------
// K3: HMMA decoder GEMM + register-resident likelihood + fused final reduce.
// ---------------------------------------------------------------------------
#define PITCH 88
#define OFF_W 0
#define OFF_H 67584
#define OFF_X 78848
#define K3_SMEM 82944

__global__ __launch_bounds__(256) void k3_decoder_m(const float* __restrict__ x,
                                                    const float* __restrict__ Wd,
                                                    const float* __restrict__ bd,
                                                    float* __restrict__ out) {
    extern __shared__ char smem[];
    __shared__ float red[8];
    __shared__ double sred[8];
    __shared__ unsigned int isLast;
    const uint32_t sb = smem_u32(smem);
    const int t = threadIdx.x;
    const int lane = t & 31;
    const int wid = t >> 5;
    const int rwarp = wid & 3;
    const int cwarp = wid >> 2;
    const int d0 = blockIdx.x * 16;

    __half* wsm = (__half*)(smem + OFF_W);
    __half* hsm = (__half*)(smem + OFF_H);
    float* xsf = (float*)(smem + OFF_X);

    for (int s = 0; s < 96; s++) {
        int idx = t + 256 * s;
        int k = idx / 384;
        int c = idx - k * 384;
        int cg = (c >> 7) * 2048 + ((c >> 4) & 7) * 256 + d0 + (c & 15);
        wsm[c * PITCH + k] = __float2half_rn(Wd[k * 6144 + cg]);
    }
    for (int i = t; i < 384 * 16; i += 256) {
        int c = i >> 4, kk = 64 + (i & 15);
        float v = 0.f;
        if (kk == 64) {
            int cg = (c >> 7) * 2048 + ((c >> 4) & 7) * 256 + d0 + (c & 15);
            v = bd[cg];
        }
        wsm[c * PITCH + kk] = __float2half_rn(v);
    }
    for (int i = t; i < 64 * 16; i += 256) {
        int r = i >> 4, kk = 64 + (i & 15);
        hsm[r * PITCH + kk] = (kk == 64) ? __float2half_rn(1.f) : __float2half_rn(0.f);
    }

    const uint32_t a_base = sb + OFF_H +
        (uint32_t)(((rwarp * 16 + (lane & 15)) * PITCH + ((lane >> 4) << 3)) * 2);
    uint32_t b_base;
    {
        int q = lane >> 3;
        int col0 = ((q >= 2) ? 16 : 0) + (lane & 7) + 8 * cwarp;
        b_base = sb + OFF_W + (uint32_t)((col0 * PITCH + (q & 1) * 8) * 2);
    }

    const int groupr = lane >> 2, qr = lane & 3;
    float episum = 0.f;

#pragma unroll 1
    for (int it = 0; it < 4; it++) {
        const int row0 = blockIdx.y * 256 + it * 64;
        __syncthreads();
        {
            const uint4* src = (const uint4*)g_h_h;
#pragma unroll
            for (int s = 0; s < 2; s++) {
                int idx = t + 256 * s;
                int r = idx >> 3, seg = idx & 7;
                uint4 v = src[(row0 + r) * 8 + seg];
                *(uint4*)&hsm[r * PITCH + seg * 8] = v;
            }
        }
#pragma unroll
        for (int s = 0; s < 4; s++) {
            int idx = t + 256 * s;
            int r = idx >> 4, dd = idx & 15;
            xsf[idx] = x[((row0 + r) & 2047) * 256 + d0 + dd];
        }
        __syncthreads();

        float acc[24][4];
#pragma unroll
        for (int j = 0; j < 24; j++)
#pragma unroll
            for (int e = 0; e < 4; e++) acc[j][e] = 0.f;

#pragma unroll
        for (int ks = 0; ks < 5; ks++) {
            uint32_t a0, a1, a2, a3;
            asm volatile("ldmatrix.sync.aligned.m8n8.x4.shared.b16 {%0,%1,%2,%3}, [%4];"
                         : "=r"(a0), "=r"(a1), "=r"(a2), "=r"(a3)
                         : "r"(a_base + ks * 32));
#pragma unroll
            for (int p = 0; p < 12; p++) {
                uint32_t b0, b1, b2, b3;
                asm volatile("ldmatrix.sync.aligned.m8n8.x4.shared.b16 {%0,%1,%2,%3}, [%4];"
                             : "=r"(b0), "=r"(b1), "=r"(b2), "=r"(b3)
                             : "r"(b_base + p * (32 * PITCH * 2) + ks * 32));
                asm volatile("mma.sync.aligned.m16n8k16.row.col.f32.f16.f16.f32 "
                             "{%0,%1,%2,%3}, {%4,%5,%6,%7}, {%8,%9}, {%0,%1,%2,%3};"
                             : "+f"(acc[2 * p][0]), "+f"(acc[2 * p][1]),
                               "+f"(acc[2 * p][2]), "+f"(acc[2 * p][3])
                             : "r"(a0), "r"(a1), "r"(a2), "r"(a3), "r"(b0), "r"(b1));
                asm volatile("mma.sync.aligned.m16n8k16.row.col.f32.f16.f16.f32 "
                             "{%0,%1,%2,%3}, {%4,%5,%6,%7}, {%8,%9}, {%0,%1,%2,%3};"
                             : "+f"(acc[2 * p + 1][0]), "+f"(acc[2 * p + 1][1]),
                               "+f"(acc[2 * p + 1][2]), "+f"(acc[2 * p + 1][3])
                             : "r"(a0), "r"(a1), "r"(a2), "r"(a3), "r"(b2), "r"(b3));
            }
        }

#pragma unroll
        for (int hh = 0; hh < 2; hh++) {
            const int r_loc = rwarp * 16 + groupr + 8 * hh;
#pragma unroll
            for (int par = 0; par < 2; par++) {
                const int e = 2 * hh + par;
                const int dd = 8 * cwarp + 2 * qr + par;
                const float xv = xsf[r_loc * 16 + dd];
                float a8[8];
                float amax = -1e30f;
#pragma unroll
                for (int k = 0; k < 8; k++) {
                    a8[k] = acc[16 + k][e];
                    amax = fmaxf(amax, a8[k]);
                }
                float se = 0.f;
#pragma unroll
                for (int k = 0; k < 8; k++) se += __expf(a8[k] - amax);
                const float lse_a = amax + __logf(se);
                float tvv[8];
                float tmax = -1e30f;
#pragma unroll
                for (int k = 0; k < 8; k++) {
                    float lpv = acc[8 + k][e];
                    float dx = xv - acc[k][e];
                    float v = a8[k] + 0.5f * lpv - 0.5f * __expf(lpv) * dx * dx;
                    tvv[k] = v;
                    tmax = fmaxf(tmax, v);
                }
                float ts = 0.f;
#pragma unroll
                for (int k = 0; k < 8; k++) ts += __expf(tvv[k] - tmax);
                episum += tmax + __logf(ts) - lse_a;
            }
        }
    }

    float v = episum;
#pragma unroll
    for (int off = 16; off > 0; off >>= 1)
        v += __shfl_down_sync(0xffffffffu, v, off);
    if (lane == 0) red[wid] = v;
    __syncthreads();
    if (t == 0) {
        float s = 0.f;
#pragma unroll
        for (int w = 0; w < 8; w++) s += red[w];
        g_part[blockIdx.y * 16 + blockIdx.x] = s;
        __threadfence();
        isLast = (atomicAdd(&g_done, 1u) == 1023u) ? 1u : 0u;
    }
    __syncthreads();

    if (isLast) {
        double s = 0.0;
        for (int i = t; i < 1024; i += 256) s += (double)g_part[i];
        for (int i = t; i < 4096; i += 256) s += (double)g_row[i];
#pragma unroll
        for (int off = 16; off > 0; off >>= 1)
            s += __shfl_down_sync(0xffffffffu, s, off);
        if (lane == 0) sred[wid] = s;
        __syncthreads();
        if (wid == 0) {
            double vv = (lane < 8) ? sred[lane] : 0.0;
#pragma unroll
            for (int off = 4; off > 0; off >>= 1)
                vv += __shfl_down_sync(0xffffffffu, vv, off);
            if (lane == 0) {
                out[0] = (float)(-vv / 16384.0 + 128.0 * 1.8378770664093453);
                g_done = 0;
            }
        }
    }
}

extern "C" void kernel_launch(void* const* d_in, const int* in_sizes, int n_in,
                              void* d_out, int out_size) {
    const float* x   = (const float*)d_in[0];
    const float* We  = (const float*)d_in[1];
    const float* be  = (const float*)d_in[2];
    const float* Wd  = (const float*)d_in[3];
    const float* bdv = (const float*)d_in[4];
    const float* ue  = (const float*)d_in[5];
    const float* rr  = (const float*)d_in[6];
    float* out = (float*)d_out;

    static int smem_set = 0;
    if (!smem_set) {
        cudaFuncSetAttribute(k3_decoder_m, cudaFuncAttributeMaxDynamicSharedMemorySize, K3_SMEM);
        smem_set = 1;
    }

    k0_prep<<<2432, 256>>>(x, We);
    k1_hmma<<<dim3(12, 16), 256>>>(be);
    k2_encoder<<<4096, 256>>>(ue, rr);
    k3_decoder_m<<<dim3(16, 64), 256, K3_SMEM>>>(x, Wd, bdv, out);
}

// round 11
// speedup vs baseline: 4.7273x; 1.1279x over previous
#include <cuda_runtime.h>
#include <cuda_fp16.h>
#include <cstdint>

#define NN 16384
#define BATCH 2048

typedef unsigned long long ull;

__device__ __forceinline__ uint32_t smem_u32(const void* p) {
    uint32_t a;
    asm("{ .reg .u64 t; cvta.to.shared.u64 t, %1; cvt.u32.u64 %0, t; }" : "=r"(a) : "l"(p));
    return a;
}

// Scratch
__device__ float g_pred_e[BATCH * 1536];
__device__ __align__(16) unsigned short g_h_h[NN * 80];        // h fp16, pitch 80 (k64=1, 65..79=0)
__device__ __align__(16) unsigned short g_x16[BATCH * 768];    // [x_hi | x_lo | x_hi]
__device__ __align__(16) unsigned short g_w16[1536 * 768];     // per col: [W_hi ; W_hi ; W_lo]
__device__ __align__(16) unsigned short g_wd16d[6144 * 80];    // Wd packed [chunk][tile][comp][dd][k80]
__device__ float g_row[4096];
__device__ float g_part[1024];
__device__ unsigned int g_done;

// ---------------------------------------------------------------------------
// K0: prep. blocks 0..2047: x hi/lo split. 2048..2431: We transpose+split.
// 2432..2815: Wd pack into k3 column order (k 0..63). 2816..2839: bias+pad.
// ---------------------------------------------------------------------------
__global__ __launch_bounds__(256) void k0_prep(const float* __restrict__ x,
                                               const float* __restrict__ We,
                                               const float* __restrict__ Wd,
                                               const float* __restrict__ bd) {
    __shared__ float tile[32][33];
    const int b = blockIdx.x;
    const int t = threadIdx.x;
    if (b < 2048) {
        int i = b * 256 + t;
        if (i == 0) g_done = 0;
        int r = i >> 8, c = i & 255;
        float v = x[i];
        __half hi = __float2half_rn(v);
        __half lo = __float2half_rn(v - __half2float(hi));
        g_x16[r * 768 + c]       = __half_as_ushort(hi);
        g_x16[r * 768 + 256 + c] = __half_as_ushort(lo);
        g_x16[r * 768 + 512 + c] = __half_as_ushort(hi);
    } else if (b < 2432) {
        int wb = b - 2048;           // 0..383
        int bk = wb & 7, bn = wb >> 3;
        int tx = t & 31, ty = t >> 5;
#pragma unroll
        for (int s = 0; s < 4; s++)
            tile[ty + 8 * s][tx] = We[(bk * 32 + ty + 8 * s) * 1536 + bn * 32 + tx];
        __syncthreads();
#pragma unroll
        for (int s = 0; s < 4; s++) {
            int nl = ty + 8 * s;
            float v = tile[tx][nl];
            __half hi = __float2half_rn(v);
            __half lo = __float2half_rn(v - __half2float(hi));
            unsigned short* gw = g_w16 + (bn * 32 + nl) * 768 + bk * 32 + tx;
            gw[0]   = __half_as_ushort(hi);
            gw[256] = __half_as_ushort(hi);
            gw[512] = __half_as_ushort(lo);
        }
    } else if (b < 2816) {
        // Wd pack: 2 k-tiles x 192 s-tiles of 32x32
        int wb = b - 2432;
        int bk = wb & 1, bs = wb >> 1;
        int tx = t & 31, ty = t >> 5;
#pragma unroll
        for (int s = 0; s < 4; s++)
            tile[ty + 8 * s][tx] = Wd[(bk * 32 + ty + 8 * s) * 6144 + bs * 32 + tx];
        __syncthreads();
        int s = bs * 32 + tx;
        int dd = s & 15, chunk = (s >> 4) & 15, comp = (s >> 8) & 7, tl = s >> 11;
        int dest = chunk * 384 + tl * 128 + comp * 16 + dd;
        __half2 p0 = __floats2half2_rn(tile[ty * 4 + 0][tx], tile[ty * 4 + 1][tx]);
        __half2 p1 = __floats2half2_rn(tile[ty * 4 + 2][tx], tile[ty * 4 + 3][tx]);
        uint2 u;
        u.x = *(uint32_t*)&p0;
        u.y = *(uint32_t*)&p1;
        *(uint2*)&g_wd16d[dest * 80 + bk * 32 + ty * 4] = u;
    } else {
        // bias (k=64) + zero pad (65..79), dest-ordered
        int cd = (b - 2816) * 256 + t;
        int chunk = cd / 384;
        int rem = cd - chunk * 384;
        int tl = rem >> 7, comp = (rem >> 4) & 7, dd = rem & 15;
        int gcol = tl * 2048 + comp * 256 + chunk * 16 + dd;
        __half hb = __float2half_rn(bd[gcol]);
        uint4 first;
        first.x = (uint32_t)__half_as_ushort(hb);
        first.y = 0; first.z = 0; first.w = 0;
        uint4 z = {0, 0, 0, 0};
        *(uint4*)&g_wd16d[cd * 80 + 64] = first;
        *(uint4*)&g_wd16d[cd * 80 + 72] = z;
    }
}

// ---------------------------------------------------------------------------
// K1: encoder GEMM on HMMA. pred_e[2048x1536] = A[2048x768]*B[768x1536]+be
// ---------------------------------------------------------------------------
#define K1P 72
__global__ __launch_bounds__(256) void k1_hmma(const float* __restrict__ be) {
    __shared__ __align__(16) __half Asm[128 * K1P];
    __shared__ __align__(16) __half Bsm[128 * K1P];
    const int t = threadIdx.x, lane = t & 31, wid = t >> 5;
    const int rwarp = wid & 3, cwarp = wid >> 2;
    const int rows0 = blockIdx.y * 128, cols0 = blockIdx.x * 128;

    float acc[2][4][2][4];
#pragma unroll
    for (int mt = 0; mt < 2; mt++)
#pragma unroll
        for (int p = 0; p < 4; p++)
#pragma unroll
            for (int pr = 0; pr < 2; pr++)
#pragma unroll
                for (int e = 0; e < 4; e++) acc[mt][p][pr][e] = 0.f;

    const uint32_t a_base = smem_u32(Asm) +
        (uint32_t)(((rwarp * 32 + (lane & 15)) * K1P + ((lane >> 4) << 3)) * 2);
    uint32_t b_base;
    {
        int q = lane >> 3;
        int col0 = ((q >= 2) ? 16 : 0) + (lane & 7) + 8 * cwarp;
        b_base = smem_u32(Bsm) + (uint32_t)((col0 * K1P + ((q & 1) << 3)) * 2);
    }

    const __half* gx = (const __half*)g_x16;
    const __half* gw = (const __half*)g_w16;

#pragma unroll 1
    for (int ks = 0; ks < 12; ks++) {
        __syncthreads();
#pragma unroll
        for (int s = 0; s < 4; s++) {
            int idx = t + 256 * s;
            int r = idx >> 3, seg = idx & 7;
            *(uint4*)(Asm + r * K1P + seg * 8) =
                *(const uint4*)(gx + (rows0 + r) * 768 + ks * 64 + seg * 8);
            *(uint4*)(Bsm + r * K1P + seg * 8) =
                *(const uint4*)(gw + (cols0 + r) * 768 + ks * 64 + seg * 8);
        }
        __syncthreads();
#pragma unroll
        for (int kk = 0; kk < 4; kk++) {
            uint32_t a[2][4];
#pragma unroll
            for (int mt = 0; mt < 2; mt++)
                asm volatile("ldmatrix.sync.aligned.m8n8.x4.shared.b16 {%0,%1,%2,%3}, [%4];"
                             : "=r"(a[mt][0]), "=r"(a[mt][1]), "=r"(a[mt][2]), "=r"(a[mt][3])
                             : "r"(a_base + mt * (16 * K1P * 2) + kk * 32));
#pragma unroll
            for (int p = 0; p < 4; p++) {
                uint32_t b0, b1, b2, b3;
                asm volatile("ldmatrix.sync.aligned.m8n8.x4.shared.b16 {%0,%1,%2,%3}, [%4];"
                             : "=r"(b0), "=r"(b1), "=r"(b2), "=r"(b3)
                             : "r"(b_base + p * (32 * K1P * 2) + kk * 32));
#pragma unroll
                for (int mt = 0; mt < 2; mt++) {
                    asm volatile("mma.sync.aligned.m16n8k16.row.col.f32.f16.f16.f32 "
                                 "{%0,%1,%2,%3}, {%4,%5,%6,%7}, {%8,%9}, {%0,%1,%2,%3};"
                                 : "+f"(acc[mt][p][0][0]), "+f"(acc[mt][p][0][1]),
                                   "+f"(acc[mt][p][0][2]), "+f"(acc[mt][p][0][3])
                                 : "r"(a[mt][0]), "r"(a[mt][1]), "r"(a[mt][2]), "r"(a[mt][3]),
                                   "r"(b0), "r"(b1));
                    asm volatile("mma.sync.aligned.m16n8k16.row.col.f32.f16.f16.f32 "
                                 "{%0,%1,%2,%3}, {%4,%5,%6,%7}, {%8,%9}, {%0,%1,%2,%3};"
                                 : "+f"(acc[mt][p][1][0]), "+f"(acc[mt][p][1][1]),
                                   "+f"(acc[mt][p][1][2]), "+f"(acc[mt][p][1][3])
                                 : "r"(a[mt][0]), "r"(a[mt][1]), "r"(a[mt][2]), "r"(a[mt][3]),
                                   "r"(b2), "r"(b3));
                }
            }
        }
    }

    const int groupr = lane >> 2, qr = lane & 3;
#pragma unroll
    for (int p = 0; p < 4; p++)
#pragma unroll
        for (int pr = 0; pr < 2; pr++) {
            const int cb = p * 32 + pr * 16 + 8 * cwarp + 2 * qr;
            const float2 bias = *(const float2*)(be + cols0 + cb);
#pragma unroll
            for (int mt = 0; mt < 2; mt++) {
                const int r0 = rwarp * 32 + mt * 16 + groupr;
                float2 o0 = {acc[mt][p][pr][0] + bias.x, acc[mt][p][pr][1] + bias.y};
                float2 o1 = {acc[mt][p][pr][2] + bias.x, acc[mt][p][pr][3] + bias.y};
                *(float2*)&g_pred_e[(rows0 + r0) * 1536 + cols0 + cb] = o0;
                *(float2*)&g_pred_e[(rows0 + r0 + 8) * 1536 + cols0 + cb] = o1;
            }
        }
}

// ---------------------------------------------------------------------------
// K2: encoder epilogue; writes h fp16 at pitch 80 with pad (k64=1, 65..79=0).
// ---------------------------------------------------------------------------
__global__ __launch_bounds__(256) void k2_encoder(const float* __restrict__ u_e,
                                                  const float* __restrict__ r_in) {
    __shared__ float red[8];
    const int t = threadIdx.x;
    const int n = blockIdx.x * 4 + (t >> 6);
    const int l = t & 63;
    const int b = n & 2047;
    const float* pe = g_pred_e + b * 1536;

    float m[8], lp[8], a[8];
#pragma unroll
    for (int k = 0; k < 8; k++) {
        m[k]  = pe[k * 64 + l];
        lp[k] = pe[512 + k * 64 + l];
        a[k]  = pe[1024 + k * 64 + l];
    }
    float amax = a[0];
#pragma unroll
    for (int k = 1; k < 8; k++) amax = fmaxf(amax, a[k]);
    float e[8];
    float se = 0.f;
#pragma unroll
    for (int k = 0; k < 8; k++) { e[k] = __expf(a[k] - amax); se += e[k]; }
    const float lse_a = amax + __logf(se);
    const float inv_se = 1.f / se;

    const float rv = r_in[n * 64 + l];
    float cacc = 0.f;
    int idx = 0;
#pragma unroll
    for (int k = 0; k < 8; k++) {
        cacc += e[k] * inv_se;
        idx += (rv > cacc) ? 1 : 0;
    }
    if (idx > 7) idx = 7;
    float msel = m[0], lpsel = lp[0];
#pragma unroll
    for (int k = 1; k < 8; k++)
        if (idx == k) { msel = m[k]; lpsel = lp[k]; }
    const float hv = fmaf(__expf(-0.5f * lpsel), u_e[n * 64 + l], msel);
    g_h_h[n * 80 + l] = __half_as_ushort(__float2half_rn(hv));
    if (l < 16)
        g_h_h[n * 80 + 64 + l] = (l == 0) ? __half_as_ushort(__float2half_rn(1.f)) : 0;

    float tv[8];
    float tmax = -1e30f;
#pragma unroll
    for (int k = 0; k < 8; k++) {
        float dh = hv - m[k];
        float v = (a[k] - lse_a) + 0.5f * lp[k] - 0.5f * __expf(lp[k]) * dh * dh;
        tv[k] = v;
        tmax = fmaxf(tmax, v);
    }
    float ts = 0.f;
#pragma unroll
    for (int k = 0; k < 8; k++) ts += __expf(tv[k] - tmax);
    const float Le_l = tmax + __logf(ts);

    float val = -0.5f * hv * hv - Le_l;
#pragma unroll
    for (int off = 16; off > 0; off >>= 1)
        val += __shfl_down_sync(0xffffffffu, val, off);
    if ((t & 31) == 0) red[t >> 5] = val;
    __syncthreads();
    if (t == 0) {
        float s = 0.f;
#pragma unroll
        for (int w = 0; w < 8; w++) s += red[w];
        g_row[blockIdx.x] = s;
    }
}

// ---------------------------------------------------------------------------
// K3: HMMA decoder GEMM + register likelihood + fused final reduce.
// W tile streamed as contiguous uint4 from g_wd16d (bias/pad folded).
// ---------------------------------------------------------------------------
#define PITCH 88
#define OFF_W 0
#define OFF_H 67584
#define OFF_X 78848
#define K3_SMEM 82944

__global__ __launch_bounds__(256) void k3_decoder_m(const float* __restrict__ x,
                                                    float* __restrict__ out) {
    extern __shared__ char smem[];
    __shared__ float red[8];
    __shared__ double sred[8];
    __shared__ unsigned int isLast;
    const uint32_t sb = smem_u32(smem);
    const int t = threadIdx.x;
    const int lane = t & 31;
    const int wid = t >> 5;
    const int rwarp = wid & 3;
    const int cwarp = wid >> 2;
    const int d0 = blockIdx.x * 16;

    __half* wsm = (__half*)(smem + OFF_W);
    __half* hsm = (__half*)(smem + OFF_H);
    float* xsf = (float*)(smem + OFF_X);

    // Stage W: 3840 contiguous uint4 -> pitched smem
    {
        const uint4* wsrc = (const uint4*)g_wd16d + blockIdx.x * 3840;
#pragma unroll
        for (int s = 0; s < 15; s++) {
            int idx = t + 256 * s;
            int c = idx / 10, seg = idx - c * 10;
            *(uint4*)&wsm[c * PITCH + seg * 8] = wsrc[idx];
        }
    }

    const uint32_t a_base = sb + OFF_H +
        (uint32_t)(((rwarp * 16 + (lane & 15)) * PITCH + ((lane >> 4) << 3)) * 2);
    uint32_t b_base;
    {
        int q = lane >> 3;
        int col0 = ((q >= 2) ? 16 : 0) + (lane & 7) + 8 * cwarp;
        b_base = sb + OFF_W + (uint32_t)((col0 * PITCH + (q & 1) * 8) * 2);
    }

    const int groupr = lane >> 2, qr = lane & 3;
    float episum = 0.f;

#pragma unroll 1
    for (int it = 0; it < 4; it++) {
        const int row0 = blockIdx.y * 256 + it * 64;
        __syncthreads();
        // stage h: 640 uint4
        {
            const __half* hsrc = (const __half*)g_h_h;
#pragma unroll
            for (int s = 0; s < 3; s++) {
                int idx = t + 256 * s;
                if (idx < 640) {
                    int r = idx / 10, seg = idx - r * 10;
                    *(uint4*)&hsm[r * PITCH + seg * 8] =
                        *(const uint4*)(hsrc + (row0 + r) * 80 + seg * 8);
                }
            }
        }
        // stage x: 1 float4 per thread
        {
            int r = t >> 2, d4 = (t & 3) << 2;
            *(float4*)&xsf[r * 16 + d4] = *(const float4*)&x[((row0 + r) & 2047) * 256 + d0 + d4];
        }
        __syncthreads();

        float acc[24][4];
#pragma unroll
        for (int j = 0; j < 24; j++)
#pragma unroll
            for (int e = 0; e < 4; e++) acc[j][e] = 0.f;

#pragma unroll
        for (int ks = 0; ks < 5; ks++) {
            uint32_t a0, a1, a2, a3;
            asm volatile("ldmatrix.sync.aligned.m8n8.x4.shared.b16 {%0,%1,%2,%3}, [%4];"
                         : "=r"(a0), "=r"(a1), "=r"(a2), "=r"(a3)
                         : "r"(a_base + ks * 32));
#pragma unroll
            for (int p = 0; p < 12; p++) {
                uint32_t b0, b1, b2, b3;
                asm volatile("ldmatrix.sync.aligned.m8n8.x4.shared.b16 {%0,%1,%2,%3}, [%4];"
                             : "=r"(b0), "=r"(b1), "=r"(b2), "=r"(b3)
                             : "r"(b_base + p * (32 * PITCH * 2) + ks * 32));
                asm volatile("mma.sync.aligned.m16n8k16.row.col.f32.f16.f16.f32 "
                             "{%0,%1,%2,%3}, {%4,%5,%6,%7}, {%8,%9}, {%0,%1,%2,%3};"
                             : "+f"(acc[2 * p][0]), "+f"(acc[2 * p][1]),
                               "+f"(acc[2 * p][2]), "+f"(acc[2 * p][3])
                             : "r"(a0), "r"(a1), "r"(a2), "r"(a3), "r"(b0), "r"(b1));
                asm volatile("mma.sync.aligned.m16n8k16.row.col.f32.f16.f16.f32 "
                             "{%0,%1,%2,%3}, {%4,%5,%6,%7}, {%8,%9}, {%0,%1,%2,%3};"
                             : "+f"(acc[2 * p + 1][0]), "+f"(acc[2 * p + 1][1]),
                               "+f"(acc[2 * p + 1][2]), "+f"(acc[2 * p + 1][3])
                             : "r"(a0), "r"(a1), "r"(a2), "r"(a3), "r"(b2), "r"(b3));
            }
        }

#pragma unroll
        for (int hh = 0; hh < 2; hh++) {
            const int r_loc = rwarp * 16 + groupr + 8 * hh;
#pragma unroll
            for (int par = 0; par < 2; par++) {
                const int e = 2 * hh + par;
                const int dd = 8 * cwarp + 2 * qr + par;
                const float xv = xsf[r_loc * 16 + dd];
                float a8[8];
                float amax = -1e30f;
#pragma unroll
                for (int k = 0; k < 8; k++) {
                    a8[k] = acc[16 + k][e];
                    amax = fmaxf(amax, a8[k]);
                }
                float se = 0.f;
#pragma unroll
                for (int k = 0; k < 8; k++) se += __expf(a8[k] - amax);
                const float lse_a = amax + __logf(se);
                float tvv[8];
                float tmax = -1e30f;
#pragma unroll
                for (int k = 0; k < 8; k++) {
                    float lpv = acc[8 + k][e];
                    float dx = xv - acc[k][e];
                    float v = a8[k] + 0.5f * lpv - 0.5f * __expf(lpv) * dx * dx;
                    tvv[k] = v;
                    tmax = fmaxf(tmax, v);
                }
                float ts = 0.f;
#pragma unroll
                for (int k = 0; k < 8; k++) ts += __expf(tvv[k] - tmax);
                episum += tmax + __logf(ts) - lse_a;
            }
        }
    }

    float v = episum;
#pragma unroll
    for (int off = 16; off > 0; off >>= 1)
        v += __shfl_down_sync(0xffffffffu, v, off);
    if (lane == 0) red[wid] = v;
    __syncthreads();
    if (t == 0) {
        float s = 0.f;
#pragma unroll
        for (int w = 0; w < 8; w++) s += red[w];
        g_part[blockIdx.y * 16 + blockIdx.x] = s;
        __threadfence();
        isLast = (atomicAdd(&g_done, 1u) == 1023u) ? 1u : 0u;
    }
    __syncthreads();

    if (isLast) {
        double s = 0.0;
        for (int i = t; i < 1024; i += 256) s += (double)g_part[i];
        for (int i = t; i < 4096; i += 256) s += (double)g_row[i];
#pragma unroll
        for (int off = 16; off > 0; off >>= 1)
            s += __shfl_down_sync(0xffffffffu, s, off);
        if (lane == 0) sred[wid] = s;
        __syncthreads();
        if (wid == 0) {
            double vv = (lane < 8) ? sred[lane] : 0.0;
#pragma unroll
            for (int off = 4; off > 0; off >>= 1)
                vv += __shfl_down_sync(0xffffffffu, vv, off);
            if (lane == 0) {
                out[0] = (float)(-vv / 16384.0 + 128.0 * 1.8378770664093453);
                g_done = 0;
            }
        }
    }
}

extern "C" void kernel_launch(void* const* d_in, const int* in_sizes, int n_in,
                              void* d_out, int out_size) {
    const float* x   = (const float*)d_in[0];
    const float* We  = (const float*)d_in[1];
    const float* be  = (const float*)d_in[2];
    const float* Wd  = (const float*)d_in[3];
    const float* bdv = (const float*)d_in[4];
    const float* ue  = (const float*)d_in[5];
    const float* rr  = (const float*)d_in[6];
    float* out = (float*)d_out;

    static int smem_set = 0;
    if (!smem_set) {
        cudaFuncSetAttribute(k3_decoder_m, cudaFuncAttributeMaxDynamicSharedMemorySize, K3_SMEM);
        smem_set = 1;
    }

    k0_prep<<<2840, 256>>>(x, We, Wd, bdv);
    k1_hmma<<<dim3(12, 16), 256>>>(be);
    k2_encoder<<<4096, 256>>>(ue, rr);
    k3_decoder_m<<<dim3(16, 64), 256, K3_SMEM>>>(x, out);
}